// round 14
// baseline (speedup 1.0000x reference)
#include <cuda_runtime.h>
#include <cuda_fp16.h>
#include <cstdint>
#include <cstddef>

// ---------------- problem constants ----------------
#define HID   3072
#define HEADS 24
#define HD    128
#define SEQL  2048
#define MLP   12288
#define H1Q   (3*HID)         // 9216  qkv part of lin1
#define C2K   (HID + MLP)     // 15360

// ---------------- device scratch (static, no allocations) ----------------
__device__ float  g_svec[HID];
__device__ float  g_mod [3*HID];                        // shift | scale | gate
__device__ __half g_xmodh[(size_t)SEQL*HID];            // modulated LN(x)
__device__ __half g_qkvh[(size_t)SEQL*H1Q];             // lin1 qkv out (half)
__device__ __half g_qh  [(size_t)HEADS*SEQL*HD];        // q (rope'd, pre-scaled)
__device__ __half g_kh  [(size_t)HEADS*SEQL*HD];        // k (rope'd)
__device__ __half g_vth [(size_t)HEADS*HD*SEQL];        // v transposed [h][d][l]
__device__ __half g_ch  [(size_t)SEQL*C2K];             // concat(attn, gelu)

// ---------------- helpers ----------------
__device__ __forceinline__ uint32_t smem_to_u32(const void* p) {
    uint32_t a;
    asm("{ .reg .u64 t; cvta.to.shared.u64 t, %1; cvt.u32.u64 %0, t; }" : "=r"(a) : "l"(p));
    return a;
}
__device__ __forceinline__ void cp16(uint32_t dst, const void* src) {
    asm volatile("cp.async.cg.shared.global [%0], [%1], 16;" :: "r"(dst), "l"(src) : "memory");
}
#define CP_COMMIT() asm volatile("cp.async.commit_group;" ::: "memory")
#define CP_WAIT1()  asm volatile("cp.async.wait_group 1;" ::: "memory")
#define CP_WAIT0()  asm volatile("cp.async.wait_group 0;" ::: "memory")

__device__ __forceinline__ void mma16(float* d, const uint32_t* a, const uint32_t* b) {
    asm volatile(
        "mma.sync.aligned.m16n8k16.row.col.f32.f16.f16.f32 "
        "{%0,%1,%2,%3}, {%4,%5,%6,%7}, {%8,%9}, {%0,%1,%2,%3};\n"
        : "+f"(d[0]), "+f"(d[1]), "+f"(d[2]), "+f"(d[3])
        : "r"(a[0]), "r"(a[1]), "r"(a[2]), "r"(a[3]), "r"(b[0]), "r"(b[1]));
}
__device__ __forceinline__ uint32_t h2u(__half2 h) { return *(uint32_t*)&h; }

__device__ __forceinline__ float gelu1(float x) {
    float x3 = x * x * x;
    return 0.5f * x * (1.f + tanhf(0.7978845608028654f * (x + 0.044715f * x3)));
}

// ================== FP16 tensor-core NT GEMM, fp32 B (weights) ==================
// C[m,n] = sum_k A[m,k]*B[n,k]  (+bias[n])(*gate[n])(+resid[m,n])(gelu)
// A half (cp.async), B fp32 (LDG->cvt->STS). 256x128 CTA tile, 8 warps of
// 64x64 (4x2 grid), 256 threads, K stages of 32, double-buffered.
#define BKH   32
#define LDS_K 40                    // padded row stride (halves)
#define STGB  ((256+128)*LDS_K*2)   // 30720 B per stage
#define GSMEM (2*STGB)              // 61440 B

__device__ __forceinline__ void load_A_stage(uint32_t sbase, int st,
                                             const __half* Ab, int lda, int k0, int tid) {
#pragma unroll
    for (int i = 0; i < 4; ++i) {
        const int idx = tid + i * 256, r = idx >> 2, c = idx & 3;
        cp16(sbase + st * STGB + r * (LDS_K * 2) + c * 16, Ab + (size_t)r * lda + k0 + c * 8);
    }
    CP_COMMIT();
}

__device__ __forceinline__ void ldg_B(const float* Bb, int ldb, int k0, int tid,
                                      float4 (&br)[4]) {
#pragma unroll
    for (int i = 0; i < 2; ++i) {
        const int idx = tid + i * 256, r = idx >> 2, c = idx & 3;
        const float* p = Bb + (size_t)r * ldb + k0 + c * 8;
        br[2*i]   = *(const float4*)(p);
        br[2*i+1] = *(const float4*)(p + 4);
    }
}

__device__ __forceinline__ void sts_B(char* sm, int st, int tid, const float4 (&br)[4]) {
#pragma unroll
    for (int i = 0; i < 2; ++i) {
        const int idx = tid + i * 256, r = idx >> 2, c = idx & 3;
        uint4 u;
        u.x = h2u(__floats2half2_rn(br[2*i].x,   br[2*i].y));
        u.y = h2u(__floats2half2_rn(br[2*i].z,   br[2*i].w));
        u.z = h2u(__floats2half2_rn(br[2*i+1].x, br[2*i+1].y));
        u.w = h2u(__floats2half2_rn(br[2*i+1].z, br[2*i+1].w));
        *(uint4*)(sm + (size_t)st * STGB + (256 + r) * (LDS_K * 2) + c * 16) = u;
    }
}

__global__ __launch_bounds__(256, 1)
void gemm_h(const __half* __restrict__ A, const float* __restrict__ Bf,
            const float* __restrict__ bias, const float* __restrict__ resid,
            const float* __restrict__ gate,
            float* __restrict__ Cf, __half* __restrict__ Ch, int do_gelu,
            int K, int lda, int ldb, int ldc)
{
    extern __shared__ __align__(16) char gsm[];
    char* sm = gsm;
    const uint32_t sbase = smem_to_u32(gsm);

    const int tid  = threadIdx.x;
    const int lane = tid & 31;
    const int gid  = lane >> 2;
    const int tg   = lane & 3;
    const int warp = tid >> 5;
    const int wm   = (warp >> 1) * 64;   // 0,64,128,192
    const int wn   = (warp & 1) * 64;    // 0,64

    const int bm0 = blockIdx.x * 256;
    const int bn0 = blockIdx.y * 128;
    const __half* Ab = A + (size_t)bm0 * lda;
    const float*  Bb = Bf + (size_t)bn0 * ldb;

    float acc[4][8][4];
#pragma unroll
    for (int i = 0; i < 4; ++i)
#pragma unroll
        for (int j = 0; j < 8; ++j)
#pragma unroll
            for (int v = 0; v < 4; ++v) acc[i][j][v] = 0.f;

    const int nk = K / BKH;

    // prologue
    float4 br[4];
    ldg_B(Bb, ldb, 0, tid, br);
    load_A_stage(sbase, 0, Ab, lda, 0, tid);
    sts_B(sm, 0, tid, br);
    ldg_B(Bb, ldb, BKH, tid, br);
    load_A_stage(sbase, 1, Ab, lda, BKH, tid);
    CP_WAIT1();
    __syncthreads();

    for (int kt = 0; kt < nk; ++kt) {
        const int s = kt & 1;
        const __half* Ss = (const __half*)(sm + s * STGB);
#pragma unroll
        for (int ks = 0; ks < 2; ++ks) {
            const int kb = ks * 16 + 2 * tg;
            uint32_t af[4][4];
#pragma unroll
            for (int im = 0; im < 4; ++im) {
                const __half* ap = Ss + (wm + im * 16 + gid) * LDS_K + kb;
                af[im][0] = *(const uint32_t*)(ap);
                af[im][1] = *(const uint32_t*)(ap + 8 * LDS_K);
                af[im][2] = *(const uint32_t*)(ap + 8);
                af[im][3] = *(const uint32_t*)(ap + 8 * LDS_K + 8);
            }
            uint32_t bf[8][2];
#pragma unroll
            for (int in = 0; in < 8; ++in) {
                const __half* bp = Ss + (256 + wn + in * 8 + gid) * LDS_K + kb;
                bf[in][0] = *(const uint32_t*)(bp);
                bf[in][1] = *(const uint32_t*)(bp + 8);
            }
#pragma unroll
            for (int im = 0; im < 4; ++im)
#pragma unroll
                for (int in = 0; in < 8; ++in)
                    mma16(acc[im][in], af[im], bf[in]);
        }
        __syncthreads();
        if (kt + 1 < nk) {
            sts_B(sm, s ^ 1, tid, br);               // B(kt+1)
            if (kt + 2 < nk) {
                ldg_B(Bb, ldb, (kt + 2) * BKH, tid, br);
                load_A_stage(sbase, s, Ab, lda, (kt + 2) * BKH, tid);
                CP_WAIT1();
            } else {
                CP_WAIT0();
            }
            __syncthreads();
        }
    }

    // ---------------- epilogue ----------------
    if (Ch) {
#pragma unroll
        for (int im = 0; im < 4; ++im)
#pragma unroll
            for (int in = 0; in < 8; ++in) {
                const int r = bm0 + wm + im * 16 + gid;
                const int c = bn0 + wn + in * 8 + 2 * tg;
                float v0 = acc[im][in][0], v1 = acc[im][in][1];
                float v2 = acc[im][in][2], v3 = acc[im][in][3];
                if (bias) {
                    const float2 bb = *(const float2*)(bias + c);
                    v0 += bb.x; v1 += bb.y; v2 += bb.x; v3 += bb.y;
                }
                if (do_gelu) {
                    v0 = gelu1(v0); v1 = gelu1(v1); v2 = gelu1(v2); v3 = gelu1(v3);
                }
                *(__half2*)(Ch + (size_t)r * ldc + c)       = __floats2half2_rn(v0, v1);
                *(__half2*)(Ch + (size_t)(r + 8) * ldc + c) = __floats2half2_rn(v2, v3);
            }
    } else {
#pragma unroll
        for (int im = 0; im < 4; ++im)
#pragma unroll
            for (int in = 0; in < 8; ++in) {
                const int r = bm0 + wm + im * 16 + gid;
                const int c = bn0 + wn + in * 8 + 2 * tg;
                float v0 = acc[im][in][0], v1 = acc[im][in][1];
                float v2 = acc[im][in][2], v3 = acc[im][in][3];
                if (bias) {
                    const float2 bb = *(const float2*)(bias + c);
                    v0 += bb.x; v1 += bb.y; v2 += bb.x; v3 += bb.y;
                }
                if (gate) {
                    const float2 gg = *(const float2*)(gate + c);
                    v0 *= gg.x; v1 *= gg.y; v2 *= gg.x; v3 *= gg.y;
                }
                if (resid) {
                    const float2 r0 = *(const float2*)(resid + (size_t)r * ldc + c);
                    const float2 r1 = *(const float2*)(resid + (size_t)(r + 8) * ldc + c);
                    v0 += r0.x; v1 += r0.y; v2 += r1.x; v3 += r1.y;
                }
                *(float2*)(Cf + (size_t)r * ldc + c)       = make_float2(v0, v1);
                *(float2*)(Cf + (size_t)(r + 8) * ldc + c) = make_float2(v2, v3);
            }
    }
}

// ================== flash attention ==================
// Per CTA: one head, 128 q rows. 8 warps x 16 q-rows. Q resident in smem,
// K/V 128-blocks double-buffered via cp.async. Online softmax in registers;
// P fed directly as mma A-fragments. Output -> g_ch cols [head*HD ...).
#define LK2   136                 // padded row stride (halves)
#define QT_B  (128*LK2*2)         // 34816 bytes per 128x128 tile
#define FSMEM (5*QT_B)            // Q + 2*K + 2*V = 174080

__global__ __launch_bounds__(256, 1)
void flash_attn(const __half* __restrict__ Qg, const __half* __restrict__ Kg,
                const __half* __restrict__ Vtg, __half* __restrict__ Oc)
{
    extern __shared__ __align__(16) char fsm[];
    const uint32_t bQ = smem_to_u32(fsm);

    const int tid = threadIdx.x, lane = tid & 31, wid = tid >> 5;
    const int gid = lane >> 2, tg = lane & 3;
    const int qb = blockIdx.x, head = blockIdx.y;

    const __half* Qh = Qg + ((size_t)head * SEQL + qb * 128) * HD;
    const __half* Kh = Kg + (size_t)head * SEQL * HD;
    const __half* Vh = Vtg + (size_t)head * HD * SEQL;

#pragma unroll
    for (int i = 0; i < 8; ++i) {
        const int idx = tid + i * 256, r = idx >> 4, c = idx & 15;
        cp16(bQ + r * (LK2 * 2) + c * 16, Qh + (size_t)r * HD + c * 8);
    }
    CP_COMMIT();
#pragma unroll
    for (int st = 0; st < 2; ++st) {
#pragma unroll
        for (int i = 0; i < 8; ++i) {
            const int idx = tid + i * 256, r = idx >> 4, c = idx & 15;
            cp16(bQ + QT_B * (1 + st) + r * (LK2 * 2) + c * 16,
                 Kh + (size_t)(st * 128 + r) * HD + c * 8);
            cp16(bQ + QT_B * (3 + st) + r * (LK2 * 2) + c * 16,
                 Vh + (size_t)r * SEQL + st * 128 + c * 8);
        }
        CP_COMMIT();
    }
    CP_WAIT1();
    __syncthreads();

    const __half* sQ = (const __half*)fsm + (size_t)(wid * 16) * LK2;

    float m0 = -1e30f, m1 = -1e30f, l0 = 0.f, l1 = 0.f;
    float ao[16][4];
#pragma unroll
    for (int j = 0; j < 16; ++j)
#pragma unroll
        for (int v = 0; v < 4; ++v) ao[j][v] = 0.f;

    const int nkb = SEQL / 128;
    for (int kb = 0; kb < nkb; ++kb) {
        const int s = kb & 1;
        const __half* Ks = (const __half*)(fsm + QT_B * (1 + s));
        const __half* Vs = (const __half*)(fsm + QT_B * (3 + s));

        float as[16][4];
#pragma unroll
        for (int j = 0; j < 16; ++j)
#pragma unroll
            for (int v = 0; v < 4; ++v) as[j][v] = 0.f;
#pragma unroll
        for (int ks = 0; ks < 8; ++ks) {
            const int kcol = ks * 16 + 2 * tg;
            uint32_t af[4];
            const __half* ap = sQ + gid * LK2 + kcol;
            af[0] = *(const uint32_t*)(ap);
            af[1] = *(const uint32_t*)(ap + 8 * LK2);
            af[2] = *(const uint32_t*)(ap + 8);
            af[3] = *(const uint32_t*)(ap + 8 * LK2 + 8);
#pragma unroll
            for (int jn = 0; jn < 16; ++jn) {
                uint32_t bf[2];
                const __half* bp = Ks + (jn * 8 + gid) * LK2 + kcol;
                bf[0] = *(const uint32_t*)(bp);
                bf[1] = *(const uint32_t*)(bp + 8);
                mma16(as[jn], af, bf);
            }
        }

        float mx0 = -1e30f, mx1 = -1e30f;
#pragma unroll
        for (int jn = 0; jn < 16; ++jn) {
            mx0 = fmaxf(mx0, fmaxf(as[jn][0], as[jn][1]));
            mx1 = fmaxf(mx1, fmaxf(as[jn][2], as[jn][3]));
        }
        mx0 = fmaxf(mx0, __shfl_xor_sync(0xffffffffu, mx0, 1));
        mx0 = fmaxf(mx0, __shfl_xor_sync(0xffffffffu, mx0, 2));
        mx1 = fmaxf(mx1, __shfl_xor_sync(0xffffffffu, mx1, 1));
        mx1 = fmaxf(mx1, __shfl_xor_sync(0xffffffffu, mx1, 2));
        const float mn0 = fmaxf(m0, mx0), mn1 = fmaxf(m1, mx1);
        const float al0 = __expf(m0 - mn0), al1 = __expf(m1 - mn1);
        float s0 = 0.f, s1 = 0.f;
#pragma unroll
        for (int jn = 0; jn < 16; ++jn) {
            as[jn][0] = __expf(as[jn][0] - mn0);
            as[jn][1] = __expf(as[jn][1] - mn0);
            as[jn][2] = __expf(as[jn][2] - mn1);
            as[jn][3] = __expf(as[jn][3] - mn1);
            s0 += as[jn][0] + as[jn][1];
            s1 += as[jn][2] + as[jn][3];
        }
        s0 += __shfl_xor_sync(0xffffffffu, s0, 1);
        s0 += __shfl_xor_sync(0xffffffffu, s0, 2);
        s1 += __shfl_xor_sync(0xffffffffu, s1, 1);
        s1 += __shfl_xor_sync(0xffffffffu, s1, 2);
        l0 = l0 * al0 + s0;  l1 = l1 * al1 + s1;
        m0 = mn0;  m1 = mn1;
#pragma unroll
        for (int jn = 0; jn < 16; ++jn) {
            ao[jn][0] *= al0; ao[jn][1] *= al0;
            ao[jn][2] *= al1; ao[jn][3] *= al1;
        }

#pragma unroll
        for (int kk = 0; kk < 8; ++kk) {
            uint32_t pa[4];
            pa[0] = h2u(__floats2half2_rn(as[2*kk][0],   as[2*kk][1]));
            pa[1] = h2u(__floats2half2_rn(as[2*kk][2],   as[2*kk][3]));
            pa[2] = h2u(__floats2half2_rn(as[2*kk+1][0], as[2*kk+1][1]));
            pa[3] = h2u(__floats2half2_rn(as[2*kk+1][2], as[2*kk+1][3]));
            const int kcol = kk * 16 + 2 * tg;
#pragma unroll
            for (int jn = 0; jn < 16; ++jn) {
                uint32_t bf[2];
                const __half* bp = Vs + (jn * 8 + gid) * LK2 + kcol;
                bf[0] = *(const uint32_t*)(bp);
                bf[1] = *(const uint32_t*)(bp + 8);
                mma16(ao[jn], pa, bf);
            }
        }

        __syncthreads();
        if (kb + 2 < nkb) {
            const int kn = kb + 2;
#pragma unroll
            for (int i = 0; i < 8; ++i) {
                const int idx = tid + i * 256, r = idx >> 4, c = idx & 15;
                cp16(bQ + QT_B * (1 + s) + r * (LK2 * 2) + c * 16,
                     Kh + (size_t)(kn * 128 + r) * HD + c * 8);
                cp16(bQ + QT_B * (3 + s) + r * (LK2 * 2) + c * 16,
                     Vh + (size_t)r * SEQL + kn * 128 + c * 8);
            }
            CP_COMMIT();
            CP_WAIT1();
        } else {
            CP_WAIT0();
        }
        __syncthreads();
    }

    const float i0 = 1.f / l0, i1 = 1.f / l1;
    __half* o0 = Oc + (size_t)(qb * 128 + wid * 16 + gid) * C2K + head * HD;
    __half* o1 = o0 + (size_t)8 * C2K;
#pragma unroll
    for (int jn = 0; jn < 16; ++jn) {
        const int c = jn * 8 + 2 * tg;
        *(__half2*)(o0 + c) = __floats2half2_rn(ao[jn][0] * i0, ao[jn][1] * i0);
        *(__half2*)(o1 + c) = __floats2half2_rn(ao[jn][2] * i1, ao[jn][3] * i1);
    }
}

// ================= small kernels =================

__global__ void silu_k(const float* __restrict__ v) {
    int i = blockIdx.x * blockDim.x + threadIdx.x;
    float x = v[i];
    g_svec[i] = x / (1.f + __expf(-x));
}

__global__ __launch_bounds__(256)
void mod_gemv(const float* __restrict__ W, const float* __restrict__ b) {
    const int warp = threadIdx.x >> 5, lane = threadIdx.x & 31;
    const int row  = blockIdx.x * 8 + warp;
    const float* w = W + (size_t)row * HID;
    float s = 0.f;
    for (int j = lane * 4; j < HID; j += 128) {
        float4 wv = *(const float4*)(w + j);
        float4 vv = *(const float4*)(g_svec + j);
        s += wv.x * vv.x + wv.y * vv.y + wv.z * vv.z + wv.w * vv.w;
    }
    #pragma unroll
    for (int o = 16; o; o >>= 1) s += __shfl_down_sync(0xffffffffu, s, o);
    if (!lane) g_mod[row] = s + b[row];
}

__global__ __launch_bounds__(256)
void ln_mod(const float* __restrict__ x) {
    const int l = blockIdx.x, tid = threadIdx.x;
    const float* xr = x + (size_t)l * HID;
    float4 v[3];
    float sum = 0.f, ss = 0.f;
    #pragma unroll
    for (int i = 0; i < 3; ++i) {
        v[i] = *(const float4*)(xr + (tid + i * 256) * 4);
        sum += v[i].x + v[i].y + v[i].z + v[i].w;
        ss  += v[i].x * v[i].x + v[i].y * v[i].y + v[i].z * v[i].z + v[i].w * v[i].w;
    }
    __shared__ float rs[2][8];
    #pragma unroll
    for (int o = 16; o; o >>= 1) {
        sum += __shfl_down_sync(0xffffffffu, sum, o);
        ss  += __shfl_down_sync(0xffffffffu, ss,  o);
    }
    if (!(tid & 31)) { rs[0][tid >> 5] = sum; rs[1][tid >> 5] = ss; }
    __syncthreads();
    sum = 0.f; ss = 0.f;
    #pragma unroll
    for (int i = 0; i < 8; ++i) { sum += rs[0][i]; ss += rs[1][i]; }
    const float mu   = sum * (1.f / HID);
    const float var  = ss * (1.f / HID) - mu * mu;
    const float rstd = rsqrtf(var + 1e-6f);
    #pragma unroll
    for (int i = 0; i < 3; ++i) {
        const int c = (tid + i * 256) * 4;
        float4 sh = *(const float4*)(g_mod + c);
        float4 sc = *(const float4*)(g_mod + HID + c);
        float ox = (1.f + sc.x) * ((v[i].x - mu) * rstd) + sh.x;
        float oy = (1.f + sc.y) * ((v[i].y - mu) * rstd) + sh.y;
        float oz = (1.f + sc.z) * ((v[i].z - mu) * rstd) + sh.z;
        float ow = (1.f + sc.w) * ((v[i].w - mu) * rstd) + sh.w;
        __half2* p = (__half2*)(g_xmodh + (size_t)l * HID + c);
        p[0] = __floats2half2_rn(ox, oy);
        p[1] = __floats2half2_rn(oz, ow);
    }
}

__global__ void qkv_prep(const float* __restrict__ pe,
                         const float* __restrict__ qs, const float* __restrict__ ks) {
    const int head = blockIdx.x, l = blockIdx.y, j = threadIdx.x;
    const __half* hr = g_qkvh + (size_t)l * H1Q + head * HD;
    float q0 = __half2float(hr[2*j]),         q1 = __half2float(hr[2*j + 1]);
    float k0 = __half2float(hr[HID + 2*j]),   k1 = __half2float(hr[HID + 2*j + 1]);
    float v0 = __half2float(hr[2*HID + 2*j]), v1 = __half2float(hr[2*HID + 2*j + 1]);

    float sq = q0*q0 + q1*q1, sk = k0*k0 + k1*k1;
    #pragma unroll
    for (int o = 16; o; o >>= 1) {
        sq += __shfl_down_sync(0xffffffffu, sq, o);
        sk += __shfl_down_sync(0xffffffffu, sk, o);
    }
    __shared__ float red[2][2];
    const int w = j >> 5, lane = j & 31;
    if (!lane) { red[0][w] = sq; red[1][w] = sk; }
    __syncthreads();
    const float rq = rsqrtf((red[0][0] + red[0][1]) * (1.f / HD) + 1e-6f);
    const float rk = rsqrtf((red[1][0] + red[1][1]) * (1.f / HD) + 1e-6f);

    q0 = q0 * rq * qs[2*j]; q1 = q1 * rq * qs[2*j + 1];
    k0 = k0 * rk * ks[2*j]; k1 = k1 * rk * ks[2*j + 1];

    const float* p = pe + ((size_t)l * (HD/2) + j) * 4;
    const float p00 = p[0], p01 = p[1], p10 = p[2], p11 = p[3];
    const float qo0 = p00 * q0 + p01 * q1, qo1 = p10 * q0 + p11 * q1;
    const float ko0 = p00 * k0 + p01 * k1, ko1 = p10 * k0 + p11 * k1;

    const float sm = 0.08838834764831845f;  // 1/sqrt(128)
    const size_t qoff = ((size_t)head * SEQL + l) * HD + 2*j;
    *(__half2*)(g_qh + qoff) = __floats2half2_rn(qo0 * sm, qo1 * sm);
    *(__half2*)(g_kh + qoff) = __floats2half2_rn(ko0, ko1);
    const size_t voff = ((size_t)head * HD + 2*j) * SEQL + l;
    g_vth[voff]        = __float2half_rn(v0);
    g_vth[voff + SEQL] = __float2half_rn(v1);
}

// ================= launcher =================
extern "C" void kernel_launch(void* const* d_in, const int* in_sizes, int n_in,
                              void* d_out, int out_size) {
    const float* x       = (const float*)d_in[0];
    const float* vec     = (const float*)d_in[1];
    const float* pe      = (const float*)d_in[2];
    const float* mod_w   = (const float*)d_in[3];
    const float* mod_b   = (const float*)d_in[4];
    const float* lin1_w  = (const float*)d_in[5];
    const float* lin1_b  = (const float*)d_in[6];
    const float* lin2_w  = (const float*)d_in[7];
    const float* lin2_b  = (const float*)d_in[8];
    const float* q_scale = (const float*)d_in[9];
    const float* k_scale = (const float*)d_in[10];
    float* out = (float*)d_out;

    float *p_mod;
    __half *p_xmodh, *p_qkvh, *p_qh, *p_kh, *p_vth, *p_ch;
    cudaGetSymbolAddress((void**)&p_mod,   g_mod);
    cudaGetSymbolAddress((void**)&p_xmodh, g_xmodh);
    cudaGetSymbolAddress((void**)&p_qkvh,  g_qkvh);
    cudaGetSymbolAddress((void**)&p_qh,    g_qh);
    cudaGetSymbolAddress((void**)&p_kh,    g_kh);
    cudaGetSymbolAddress((void**)&p_vth,   g_vth);
    cudaGetSymbolAddress((void**)&p_ch,    g_ch);

    cudaFuncSetAttribute(gemm_h, cudaFuncAttributeMaxDynamicSharedMemorySize, GSMEM);
    cudaFuncSetAttribute(flash_attn, cudaFuncAttributeMaxDynamicSharedMemorySize, FSMEM);

    // 1) modulation vector
    silu_k<<<HID / 256, 256>>>(vec);
    mod_gemv<<<(3 * HID) / 8, 256>>>(mod_w, mod_b);

    // 2) layernorm + modulation -> half
    ln_mod<<<SEQL, 256>>>(x);

    // 3a) lin1 qkv part: [2048 x 9216], fp32 weights converted in-GEMM
    gemm_h<<<dim3(SEQL / 256, H1Q / 128), 256, GSMEM>>>(
        p_xmodh, lin1_w, lin1_b, nullptr, nullptr, nullptr, p_qkvh, 0,
        HID, HID, HID, H1Q);

    // 3b) lin1 mlp part: [2048 x 12288], fused bias+GELU -> concat cols [HID:)
    gemm_h<<<dim3(SEQL / 256, MLP / 128), 256, GSMEM>>>(
        p_xmodh, lin1_w + (size_t)H1Q * HID, lin1_b + H1Q, nullptr, nullptr,
        nullptr, p_ch + HID, 1,
        HID, HID, HID, C2K);

    // 4) qkv prep (rmsnorm + rope + V transpose)
    qkv_prep<<<dim3(HEADS, SEQL), 64>>>(pe, q_scale, k_scale);

    // 5) flash attention -> concat cols [0:HID)
    flash_attn<<<dim3(SEQL / 128, HEADS), 256, FSMEM>>>(p_qh, p_kh, p_vth, p_ch);

    // 6) lin2 + gate + residual fused: out = x + gate * (c @ lin2_w^T + b)
    gemm_h<<<dim3(SEQL / 256, HID / 128), 256, GSMEM>>>(
        p_ch, lin2_w, lin2_b, x, p_mod + 2 * HID, out, nullptr, 0,
        C2K, C2K, C2K, HID);
}

// round 15
// speedup vs baseline: 1.0087x; 1.0087x over previous
#include <cuda_runtime.h>
#include <cuda_fp16.h>
#include <cstdint>
#include <cstddef>

// ---------------- problem constants ----------------
#define HID   3072
#define HEADS 24
#define HD    128
#define SEQL  2048
#define MLP   12288
#define H1Q   (3*HID)         // 9216  qkv part of lin1
#define C2K   (HID + MLP)     // 15360

// ---------------- device scratch (static, no allocations) ----------------
__device__ float  g_svec[HID];
__device__ float  g_mod [3*HID];                        // shift | scale | gate
__device__ float  g_sf  [(size_t)HEADS*SEQL*SEQL];      // scores fp32
__device__ __half g_xmodh[(size_t)SEQL*HID];            // modulated LN(x)
__device__ __half g_qkvh[(size_t)SEQL*H1Q];             // lin1 qkv out (half)
__device__ __half g_qh  [(size_t)HEADS*SEQL*HD];        // q (rope'd, pre-scaled)
__device__ __half g_kh  [(size_t)HEADS*SEQL*HD];        // k (rope'd)
__device__ __half g_vth [(size_t)HEADS*HD*SEQL];        // v transposed [h][d][l]
__device__ __half g_ph  [(size_t)HEADS*SEQL*SEQL];      // probs half
__device__ __half g_ch  [(size_t)SEQL*C2K];             // concat(attn, gelu)

// ---------------- helpers ----------------
__device__ __forceinline__ uint32_t smem_to_u32(const void* p) {
    uint32_t a;
    asm("{ .reg .u64 t; cvta.to.shared.u64 t, %1; cvt.u32.u64 %0, t; }" : "=r"(a) : "l"(p));
    return a;
}
__device__ __forceinline__ void cp16(uint32_t dst, const void* src) {
    asm volatile("cp.async.cg.shared.global [%0], [%1], 16;" :: "r"(dst), "l"(src) : "memory");
}
#define CP_COMMIT() asm volatile("cp.async.commit_group;" ::: "memory")
#define CP_WAIT1()  asm volatile("cp.async.wait_group 1;" ::: "memory")
#define CP_WAIT0()  asm volatile("cp.async.wait_group 0;" ::: "memory")

__device__ __forceinline__ void mma16(float* d, const uint32_t* a, const uint32_t* b) {
    asm volatile(
        "mma.sync.aligned.m16n8k16.row.col.f32.f16.f16.f32 "
        "{%0,%1,%2,%3}, {%4,%5,%6,%7}, {%8,%9}, {%0,%1,%2,%3};\n"
        : "+f"(d[0]), "+f"(d[1]), "+f"(d[2]), "+f"(d[3])
        : "r"(a[0]), "r"(a[1]), "r"(a[2]), "r"(a[3]), "r"(b[0]), "r"(b[1]));
}
__device__ __forceinline__ uint32_t h2u(__half2 h) { return *(uint32_t*)&h; }

__device__ __forceinline__ float gelu1(float x) {
    float x3 = x * x * x;
    return 0.5f * x * (1.f + tanhf(0.7978845608028654f * (x + 0.044715f * x3)));
}

// common tile constants: 128x128 CTA tile, 4 warps of 64x64, 128 threads
#define BKH   32
#define LDS_K 40                 // padded row stride (halves)
#define STGB  (256*LDS_K*2)      // 20480 B per stage (128 A rows + 128 B rows)

// ================== GEMM variant 1: both operands half (attention) ==================
// C[b,m,n] = sum_k A[b,m,k]*B[b,n,k]; out fp32 (Cf) or half (Ch)
__global__ __launch_bounds__(128, 2)
void gemm_hh(const __half* __restrict__ A, const __half* __restrict__ B,
             float* __restrict__ Cf, __half* __restrict__ Ch,
             int K, int lda, int ldb, int ldc,
             long long sA, long long sB, long long sC)
{
    __shared__ __align__(16) __half smbuf[2 * 256 * LDS_K];
    char* sm = (char*)smbuf;
    const uint32_t sbase = smem_to_u32(smbuf);

    const int tid  = threadIdx.x;
    const int lane = tid & 31;
    const int gid  = lane >> 2;
    const int tg   = lane & 3;
    const int warp = tid >> 5;
    const int wm   = (warp >> 1) * 64;
    const int wn   = (warp & 1) * 64;

    const int bm0 = blockIdx.x * 128;
    const int bn0 = blockIdx.y * 128;
    const __half* Ab = A + (size_t)blockIdx.z * sA + (size_t)bm0 * lda;
    const __half* Bb = B + (size_t)blockIdx.z * sB + (size_t)bn0 * ldb;

    float acc[4][8][4];
#pragma unroll
    for (int i = 0; i < 4; ++i)
#pragma unroll
        for (int j = 0; j < 8; ++j)
#pragma unroll
            for (int v = 0; v < 4; ++v) acc[i][j][v] = 0.f;

    const int nk = K / BKH;

#define LOAD_STAGE_HH(k0, st) do {                                           \
    _Pragma("unroll")                                                        \
    for (int _i = 0; _i < 8; ++_i) {                                         \
        const int _idx = tid + _i * 128;                                     \
        const int _r = _idx >> 2, _c = _idx & 3;                             \
        const __half* _src = (_r < 128)                                      \
            ? Ab + (size_t)_r * lda + (k0) + _c * 8                          \
            : Bb + (size_t)(_r - 128) * ldb + (k0) + _c * 8;                 \
        cp16(sbase + (st) * STGB + _r * (LDS_K * 2) + _c * 16, _src);        \
    }                                                                        \
    CP_COMMIT();                                                             \
} while (0)

    LOAD_STAGE_HH(0, 0);
    LOAD_STAGE_HH(BKH, 1);

    for (int kt = 0; kt < nk; ++kt) {
        const int s = kt & 1;
        if (kt == nk - 1) CP_WAIT0(); else CP_WAIT1();
        __syncthreads();

        const __half* Ss = (const __half*)(sm + s * STGB);
#pragma unroll
        for (int ks = 0; ks < 2; ++ks) {
            const int kb = ks * 16 + 2 * tg;
            uint32_t af[4][4];
#pragma unroll
            for (int im = 0; im < 4; ++im) {
                const __half* ap = Ss + (wm + im * 16 + gid) * LDS_K + kb;
                af[im][0] = *(const uint32_t*)(ap);
                af[im][1] = *(const uint32_t*)(ap + 8 * LDS_K);
                af[im][2] = *(const uint32_t*)(ap + 8);
                af[im][3] = *(const uint32_t*)(ap + 8 * LDS_K + 8);
            }
            uint32_t bf[8][2];
#pragma unroll
            for (int in = 0; in < 8; ++in) {
                const __half* bp = Ss + (128 + wn + in * 8 + gid) * LDS_K + kb;
                bf[in][0] = *(const uint32_t*)(bp);
                bf[in][1] = *(const uint32_t*)(bp + 8);
            }
#pragma unroll
            for (int im = 0; im < 4; ++im)
#pragma unroll
                for (int in = 0; in < 8; ++in)
                    mma16(acc[im][in], af[im], bf[in]);
        }
        __syncthreads();
        if (kt + 2 < nk) LOAD_STAGE_HH((kt + 2) * BKH, s);
    }
#undef LOAD_STAGE_HH

    if (Ch) {
        __half* Cb = Ch + (size_t)blockIdx.z * sC;
#pragma unroll
        for (int im = 0; im < 4; ++im)
#pragma unroll
            for (int in = 0; in < 8; ++in) {
                const int r = bm0 + wm + im * 16 + gid;
                const int c = bn0 + wn + in * 8 + 2 * tg;
                *(__half2*)(Cb + (size_t)r * ldc + c) =
                    __floats2half2_rn(acc[im][in][0], acc[im][in][1]);
                *(__half2*)(Cb + (size_t)(r + 8) * ldc + c) =
                    __floats2half2_rn(acc[im][in][2], acc[im][in][3]);
            }
    } else {
        float* Cb = Cf + (size_t)blockIdx.z * sC;
#pragma unroll
        for (int im = 0; im < 4; ++im)
#pragma unroll
            for (int in = 0; in < 8; ++in) {
                const int r = bm0 + wm + im * 16 + gid;
                const int c = bn0 + wn + in * 8 + 2 * tg;
                *(float2*)(Cb + (size_t)r * ldc + c) =
                    make_float2(acc[im][in][0], acc[im][in][1]);
                *(float2*)(Cb + (size_t)(r + 8) * ldc + c) =
                    make_float2(acc[im][in][2], acc[im][in][3]);
            }
    }
}

// ================== GEMM variant 2: A half, B fp32 weights (lin1/lin2) ==================
// C[m,n] = sum_k A[m,k]*B[n,k]  (+bias[n])(*gate[n])(+resid[m,n])(gelu)
__device__ __forceinline__ void load_A_stage(uint32_t sbase, int st,
                                             const __half* Ab, int lda, int k0, int tid) {
#pragma unroll
    for (int i = 0; i < 4; ++i) {
        const int idx = tid + i * 128, r = idx >> 2, c = idx & 3;
        cp16(sbase + st * STGB + r * (LDS_K * 2) + c * 16, Ab + (size_t)r * lda + k0 + c * 8);
    }
    CP_COMMIT();
}

__device__ __forceinline__ void ldg_B(const float* Bb, int ldb, int k0, int tid,
                                      float4 (&br)[8]) {
#pragma unroll
    for (int i = 0; i < 4; ++i) {
        const int idx = tid + i * 128, r = idx >> 2, c = idx & 3;
        const float* p = Bb + (size_t)r * ldb + k0 + c * 8;
        br[2*i]   = *(const float4*)(p);
        br[2*i+1] = *(const float4*)(p + 4);
    }
}

__device__ __forceinline__ void sts_B(char* sm, int st, int tid, const float4 (&br)[8]) {
#pragma unroll
    for (int i = 0; i < 4; ++i) {
        const int idx = tid + i * 128, r = idx >> 2, c = idx & 3;
        uint4 u;
        u.x = h2u(__floats2half2_rn(br[2*i].x,   br[2*i].y));
        u.y = h2u(__floats2half2_rn(br[2*i].z,   br[2*i].w));
        u.z = h2u(__floats2half2_rn(br[2*i+1].x, br[2*i+1].y));
        u.w = h2u(__floats2half2_rn(br[2*i+1].z, br[2*i+1].w));
        *(uint4*)(sm + (size_t)st * STGB + (128 + r) * (LDS_K * 2) + c * 16) = u;
    }
}

__global__ __launch_bounds__(128, 2)
void gemm_wf(const __half* __restrict__ A, const float* __restrict__ Bf,
             const float* __restrict__ bias, const float* __restrict__ resid,
             const float* __restrict__ gate,
             float* __restrict__ Cf, __half* __restrict__ Ch, int do_gelu,
             int K, int lda, int ldb, int ldc)
{
    __shared__ __align__(16) __half smbuf[2 * 256 * LDS_K];
    char* sm = (char*)smbuf;
    const uint32_t sbase = smem_to_u32(smbuf);

    const int tid  = threadIdx.x;
    const int lane = tid & 31;
    const int gid  = lane >> 2;
    const int tg   = lane & 3;
    const int warp = tid >> 5;
    const int wm   = (warp >> 1) * 64;
    const int wn   = (warp & 1) * 64;

    const int bm0 = blockIdx.x * 128;
    const int bn0 = blockIdx.y * 128;
    const __half* Ab = A + (size_t)bm0 * lda;
    const float*  Bb = Bf + (size_t)bn0 * ldb;

    float acc[4][8][4];
#pragma unroll
    for (int i = 0; i < 4; ++i)
#pragma unroll
        for (int j = 0; j < 8; ++j)
#pragma unroll
            for (int v = 0; v < 4; ++v) acc[i][j][v] = 0.f;

    const int nk = K / BKH;

    float4 br[8];
    ldg_B(Bb, ldb, 0, tid, br);
    load_A_stage(sbase, 0, Ab, lda, 0, tid);
    sts_B(sm, 0, tid, br);
    ldg_B(Bb, ldb, BKH, tid, br);
    load_A_stage(sbase, 1, Ab, lda, BKH, tid);
    CP_WAIT1();
    __syncthreads();

    for (int kt = 0; kt < nk; ++kt) {
        const int s = kt & 1;
        const __half* Ss = (const __half*)(sm + s * STGB);
#pragma unroll
        for (int ks = 0; ks < 2; ++ks) {
            const int kb = ks * 16 + 2 * tg;
            uint32_t af[4][4];
#pragma unroll
            for (int im = 0; im < 4; ++im) {
                const __half* ap = Ss + (wm + im * 16 + gid) * LDS_K + kb;
                af[im][0] = *(const uint32_t*)(ap);
                af[im][1] = *(const uint32_t*)(ap + 8 * LDS_K);
                af[im][2] = *(const uint32_t*)(ap + 8);
                af[im][3] = *(const uint32_t*)(ap + 8 * LDS_K + 8);
            }
            uint32_t bf[8][2];
#pragma unroll
            for (int in = 0; in < 8; ++in) {
                const __half* bp = Ss + (128 + wn + in * 8 + gid) * LDS_K + kb;
                bf[in][0] = *(const uint32_t*)(bp);
                bf[in][1] = *(const uint32_t*)(bp + 8);
            }
#pragma unroll
            for (int im = 0; im < 4; ++im)
#pragma unroll
                for (int in = 0; in < 8; ++in)
                    mma16(acc[im][in], af[im], bf[in]);
        }
        __syncthreads();
        if (kt + 1 < nk) {
            sts_B(sm, s ^ 1, tid, br);
            if (kt + 2 < nk) {
                ldg_B(Bb, ldb, (kt + 2) * BKH, tid, br);
                load_A_stage(sbase, s, Ab, lda, (kt + 2) * BKH, tid);
                CP_WAIT1();
            } else {
                CP_WAIT0();
            }
            __syncthreads();
        }
    }

    if (Ch) {
#pragma unroll
        for (int im = 0; im < 4; ++im)
#pragma unroll
            for (int in = 0; in < 8; ++in) {
                const int r = bm0 + wm + im * 16 + gid;
                const int c = bn0 + wn + in * 8 + 2 * tg;
                float v0 = acc[im][in][0], v1 = acc[im][in][1];
                float v2 = acc[im][in][2], v3 = acc[im][in][3];
                if (bias) {
                    const float2 bb = *(const float2*)(bias + c);
                    v0 += bb.x; v1 += bb.y; v2 += bb.x; v3 += bb.y;
                }
                if (do_gelu) {
                    v0 = gelu1(v0); v1 = gelu1(v1); v2 = gelu1(v2); v3 = gelu1(v3);
                }
                *(__half2*)(Ch + (size_t)r * ldc + c)       = __floats2half2_rn(v0, v1);
                *(__half2*)(Ch + (size_t)(r + 8) * ldc + c) = __floats2half2_rn(v2, v3);
            }
    } else {
#pragma unroll
        for (int im = 0; im < 4; ++im)
#pragma unroll
            for (int in = 0; in < 8; ++in) {
                const int r = bm0 + wm + im * 16 + gid;
                const int c = bn0 + wn + in * 8 + 2 * tg;
                float v0 = acc[im][in][0], v1 = acc[im][in][1];
                float v2 = acc[im][in][2], v3 = acc[im][in][3];
                if (bias) {
                    const float2 bb = *(const float2*)(bias + c);
                    v0 += bb.x; v1 += bb.y; v2 += bb.x; v3 += bb.y;
                }
                if (gate) {
                    const float2 gg = *(const float2*)(gate + c);
                    v0 *= gg.x; v1 *= gg.y; v2 *= gg.x; v3 *= gg.y;
                }
                if (resid) {
                    const float2 r0 = *(const float2*)(resid + (size_t)r * ldc + c);
                    const float2 r1 = *(const float2*)(resid + (size_t)(r + 8) * ldc + c);
                    v0 += r0.x; v1 += r0.y; v2 += r1.x; v3 += r1.y;
                }
                *(float2*)(Cf + (size_t)r * ldc + c)       = make_float2(v0, v1);
                *(float2*)(Cf + (size_t)(r + 8) * ldc + c) = make_float2(v2, v3);
            }
    }
}

// ================= small kernels =================

__global__ void silu_k(const float* __restrict__ v) {
    int i = blockIdx.x * blockDim.x + threadIdx.x;
    float x = v[i];
    g_svec[i] = x / (1.f + __expf(-x));
}

__global__ __launch_bounds__(256)
void mod_gemv(const float* __restrict__ W, const float* __restrict__ b) {
    const int warp = threadIdx.x >> 5, lane = threadIdx.x & 31;
    const int row  = blockIdx.x * 8 + warp;
    const float* w = W + (size_t)row * HID;
    float s = 0.f;
    for (int j = lane * 4; j < HID; j += 128) {
        float4 wv = *(const float4*)(w + j);
        float4 vv = *(const float4*)(g_svec + j);
        s += wv.x * vv.x + wv.y * vv.y + wv.z * vv.z + wv.w * vv.w;
    }
    #pragma unroll
    for (int o = 16; o; o >>= 1) s += __shfl_down_sync(0xffffffffu, s, o);
    if (!lane) g_mod[row] = s + b[row];
}

__global__ __launch_bounds__(256)
void ln_mod(const float* __restrict__ x) {
    const int l = blockIdx.x, tid = threadIdx.x;
    const float* xr = x + (size_t)l * HID;
    float4 v[3];
    float sum = 0.f, ss = 0.f;
    #pragma unroll
    for (int i = 0; i < 3; ++i) {
        v[i] = *(const float4*)(xr + (tid + i * 256) * 4);
        sum += v[i].x + v[i].y + v[i].z + v[i].w;
        ss  += v[i].x * v[i].x + v[i].y * v[i].y + v[i].z * v[i].z + v[i].w * v[i].w;
    }
    __shared__ float rs[2][8];
    #pragma unroll
    for (int o = 16; o; o >>= 1) {
        sum += __shfl_down_sync(0xffffffffu, sum, o);
        ss  += __shfl_down_sync(0xffffffffu, ss,  o);
    }
    if (!(tid & 31)) { rs[0][tid >> 5] = sum; rs[1][tid >> 5] = ss; }
    __syncthreads();
    sum = 0.f; ss = 0.f;
    #pragma unroll
    for (int i = 0; i < 8; ++i) { sum += rs[0][i]; ss += rs[1][i]; }
    const float mu   = sum * (1.f / HID);
    const float var  = ss * (1.f / HID) - mu * mu;
    const float rstd = rsqrtf(var + 1e-6f);
    #pragma unroll
    for (int i = 0; i < 3; ++i) {
        const int c = (tid + i * 256) * 4;
        float4 sh = *(const float4*)(g_mod + c);
        float4 sc = *(const float4*)(g_mod + HID + c);
        float ox = (1.f + sc.x) * ((v[i].x - mu) * rstd) + sh.x;
        float oy = (1.f + sc.y) * ((v[i].y - mu) * rstd) + sh.y;
        float oz = (1.f + sc.z) * ((v[i].z - mu) * rstd) + sh.z;
        float ow = (1.f + sc.w) * ((v[i].w - mu) * rstd) + sh.w;
        __half2* p = (__half2*)(g_xmodh + (size_t)l * HID + c);
        p[0] = __floats2half2_rn(ox, oy);
        p[1] = __floats2half2_rn(oz, ow);
    }
}

__global__ void qkv_prep(const float* __restrict__ pe,
                         const float* __restrict__ qs, const float* __restrict__ ks) {
    const int head = blockIdx.x, l = blockIdx.y, j = threadIdx.x;
    const __half* hr = g_qkvh + (size_t)l * H1Q + head * HD;
    float q0 = __half2float(hr[2*j]),         q1 = __half2float(hr[2*j + 1]);
    float k0 = __half2float(hr[HID + 2*j]),   k1 = __half2float(hr[HID + 2*j + 1]);
    float v0 = __half2float(hr[2*HID + 2*j]), v1 = __half2float(hr[2*HID + 2*j + 1]);

    float sq = q0*q0 + q1*q1, sk = k0*k0 + k1*k1;
    #pragma unroll
    for (int o = 16; o; o >>= 1) {
        sq += __shfl_down_sync(0xffffffffu, sq, o);
        sk += __shfl_down_sync(0xffffffffu, sk, o);
    }
    __shared__ float red[2][2];
    const int w = j >> 5, lane = j & 31;
    if (!lane) { red[0][w] = sq; red[1][w] = sk; }
    __syncthreads();
    const float rq = rsqrtf((red[0][0] + red[0][1]) * (1.f / HD) + 1e-6f);
    const float rk = rsqrtf((red[1][0] + red[1][1]) * (1.f / HD) + 1e-6f);

    q0 = q0 * rq * qs[2*j]; q1 = q1 * rq * qs[2*j + 1];
    k0 = k0 * rk * ks[2*j]; k1 = k1 * rk * ks[2*j + 1];

    const float* p = pe + ((size_t)l * (HD/2) + j) * 4;
    const float p00 = p[0], p01 = p[1], p10 = p[2], p11 = p[3];
    const float qo0 = p00 * q0 + p01 * q1, qo1 = p10 * q0 + p11 * q1;
    const float ko0 = p00 * k0 + p01 * k1, ko1 = p10 * k0 + p11 * k1;

    const float sm = 0.08838834764831845f;  // 1/sqrt(128)
    const size_t qoff = ((size_t)head * SEQL + l) * HD + 2*j;
    *(__half2*)(g_qh + qoff) = __floats2half2_rn(qo0 * sm, qo1 * sm);
    *(__half2*)(g_kh + qoff) = __floats2half2_rn(ko0, ko1);
    const size_t voff = ((size_t)head * HD + 2*j) * SEQL + l;
    g_vth[voff]        = __float2half_rn(v0);
    g_vth[voff + SEQL] = __float2half_rn(v1);
}

// row softmax: fp32 scores in, half probs out
__global__ __launch_bounds__(256)
void softmax_k() {
    const float* p = g_sf + (size_t)blockIdx.x * SEQL;
    __half2* q = (__half2*)(g_ph + (size_t)blockIdx.x * SEQL);
    const int tid = threadIdx.x;
    float4 v0 = *(const float4*)(p + tid * 4);
    float4 v1 = *(const float4*)(p + 1024 + tid * 4);
    float mx = fmaxf(fmaxf(fmaxf(v0.x, v0.y), fmaxf(v0.z, v0.w)),
                     fmaxf(fmaxf(v1.x, v1.y), fmaxf(v1.z, v1.w)));
    __shared__ float rs[8];
    #pragma unroll
    for (int o = 16; o; o >>= 1) mx = fmaxf(mx, __shfl_xor_sync(0xffffffffu, mx, o));
    if (!(tid & 31)) rs[tid >> 5] = mx;
    __syncthreads();
    float gmx = rs[0];
    #pragma unroll
    for (int i = 1; i < 8; ++i) gmx = fmaxf(gmx, rs[i]);
    __syncthreads();
    float sm = 0.f;
    v0.x = __expf(v0.x - gmx); sm += v0.x;  v0.y = __expf(v0.y - gmx); sm += v0.y;
    v0.z = __expf(v0.z - gmx); sm += v0.z;  v0.w = __expf(v0.w - gmx); sm += v0.w;
    v1.x = __expf(v1.x - gmx); sm += v1.x;  v1.y = __expf(v1.y - gmx); sm += v1.y;
    v1.z = __expf(v1.z - gmx); sm += v1.z;  v1.w = __expf(v1.w - gmx); sm += v1.w;
    #pragma unroll
    for (int o = 16; o; o >>= 1) sm += __shfl_xor_sync(0xffffffffu, sm, o);
    if (!(tid & 31)) rs[tid >> 5] = sm;
    __syncthreads();
    float gs = 0.f;
    #pragma unroll
    for (int i = 0; i < 8; ++i) gs += rs[i];
    const float inv = 1.f / gs;
    q[tid*2]       = __floats2half2_rn(v0.x * inv, v0.y * inv);
    q[tid*2+1]     = __floats2half2_rn(v0.z * inv, v0.w * inv);
    q[512+tid*2]   = __floats2half2_rn(v1.x * inv, v1.y * inv);
    q[512+tid*2+1] = __floats2half2_rn(v1.z * inv, v1.w * inv);
}

// ================= launcher =================
extern "C" void kernel_launch(void* const* d_in, const int* in_sizes, int n_in,
                              void* d_out, int out_size) {
    const float* x       = (const float*)d_in[0];
    const float* vec     = (const float*)d_in[1];
    const float* pe      = (const float*)d_in[2];
    const float* mod_w   = (const float*)d_in[3];
    const float* mod_b   = (const float*)d_in[4];
    const float* lin1_w  = (const float*)d_in[5];
    const float* lin1_b  = (const float*)d_in[6];
    const float* lin2_w  = (const float*)d_in[7];
    const float* lin2_b  = (const float*)d_in[8];
    const float* q_scale = (const float*)d_in[9];
    const float* k_scale = (const float*)d_in[10];
    float* out = (float*)d_out;

    float *p_mod, *p_sf;
    __half *p_xmodh, *p_qkvh, *p_qh, *p_kh, *p_vth, *p_ph, *p_ch;
    cudaGetSymbolAddress((void**)&p_mod,   g_mod);
    cudaGetSymbolAddress((void**)&p_sf,    g_sf);
    cudaGetSymbolAddress((void**)&p_xmodh, g_xmodh);
    cudaGetSymbolAddress((void**)&p_qkvh,  g_qkvh);
    cudaGetSymbolAddress((void**)&p_qh,    g_qh);
    cudaGetSymbolAddress((void**)&p_kh,    g_kh);
    cudaGetSymbolAddress((void**)&p_vth,   g_vth);
    cudaGetSymbolAddress((void**)&p_ph,    g_ph);
    cudaGetSymbolAddress((void**)&p_ch,    g_ch);

    // 1) modulation vector
    silu_k<<<HID / 256, 256>>>(vec);
    mod_gemv<<<(3 * HID) / 8, 256>>>(mod_w, mod_b);

    // 2) layernorm + modulation -> half
    ln_mod<<<SEQL, 256>>>(x);

    // 3a) lin1 qkv part: [2048 x 9216], fp32 weights converted in-GEMM
    gemm_wf<<<dim3(SEQL / 128, H1Q / 128), 128>>>(
        p_xmodh, lin1_w, lin1_b, nullptr, nullptr, nullptr, p_qkvh, 0,
        HID, HID, HID, H1Q);

    // 3b) lin1 mlp part: [2048 x 12288], fused bias+GELU -> concat cols [HID:)
    gemm_wf<<<dim3(SEQL / 128, MLP / 128), 128>>>(
        p_xmodh, lin1_w + (size_t)H1Q * HID, lin1_b + H1Q, nullptr, nullptr,
        nullptr, p_ch + HID, 1,
        HID, HID, HID, C2K);

    // 4) qkv prep (rmsnorm + rope + V transpose)
    qkv_prep<<<dim3(HEADS, SEQL), 64>>>(pe, q_scale, k_scale);

    // 5) scores = q @ k^T (batched over heads) -> fp32
    gemm_hh<<<dim3(SEQL / 128, SEQL / 128, HEADS), 128>>>(
        p_qh, p_kh, p_sf, nullptr,
        HD, HD, HD, SEQL,
        (long long)SEQL * HD, (long long)SEQL * HD, (long long)SEQL * SEQL);

    // 6) softmax -> half probs
    softmax_k<<<HEADS * SEQL, 256>>>();

    // 7) attn = P @ V -> half concat buffer cols [0:HID), head-interleaved
    gemm_hh<<<dim3(SEQL / 128, HD / 128, HEADS), 128>>>(
        p_ph, p_vth, nullptr, p_ch,
        SEQL, SEQL, SEQL, C2K,
        (long long)SEQL * SEQL, (long long)HD * SEQL, (long long)HD);

    // 8) lin2 + gate + residual fused: out = x + gate * (c @ lin2_w^T + b)
    gemm_wf<<<dim3(SEQL / 128, HID / 128), 128>>>(
        p_ch, lin2_w, lin2_b, x, p_mod + 2 * HID, out, nullptr, 0,
        C2K, C2K, C2K, HID);
}

// round 16
// speedup vs baseline: 1.1071x; 1.0975x over previous
#include <cuda_runtime.h>
#include <cuda_fp16.h>
#include <cstdint>
#include <cstddef>

// ---------------- problem constants ----------------
#define HID   3072
#define HEADS 24
#define HD    128
#define SEQL  2048
#define MLP   12288
#define H1Q   (3*HID)         // 9216
#define C2K   (HID + MLP)     // 15360

// ---------------- device scratch (static, no allocations) ----------------
__device__ float  g_svec[HID];
__device__ float  g_mod [3*HID];                        // shift | scale | gate
__device__ float  g_sf  [(size_t)HEADS*SEQL*SEQL];      // scores fp32
__device__ __half g_xmodh[(size_t)SEQL*HID];            // modulated LN(x)
__device__ __half g_w1h [(size_t)(H1Q+MLP)*HID];        // lin1_w half
__device__ __half g_w2h [(size_t)HID*C2K];              // lin2_w half
__device__ __half g_qkvh[(size_t)SEQL*H1Q];             // lin1 qkv out
__device__ __half g_qh  [(size_t)HEADS*SEQL*HD];
__device__ __half g_kh  [(size_t)HEADS*SEQL*HD];
__device__ __half g_vth [(size_t)HEADS*HD*SEQL];        // v transposed [h][d][l]
__device__ __half g_ph  [(size_t)HEADS*SEQL*SEQL];      // probs half
__device__ __half g_ch  [(size_t)SEQL*C2K];             // concat(attn, gelu)

// ---------------- helpers ----------------
__device__ __forceinline__ uint32_t smem_to_u32(const void* p) {
    uint32_t a;
    asm("{ .reg .u64 t; cvta.to.shared.u64 t, %1; cvt.u32.u64 %0, t; }" : "=r"(a) : "l"(p));
    return a;
}
__device__ __forceinline__ void cp16(uint32_t dst, const void* src) {
    asm volatile("cp.async.cg.shared.global [%0], [%1], 16;" :: "r"(dst), "l"(src) : "memory");
}
#define CP_COMMIT() asm volatile("cp.async.commit_group;" ::: "memory")
#define CP_WAIT1()  asm volatile("cp.async.wait_group 1;" ::: "memory")
#define CP_WAIT0()  asm volatile("cp.async.wait_group 0;" ::: "memory")

__device__ __forceinline__ void mma16(float* d, const uint32_t* a, const uint32_t* b) {
    asm volatile(
        "mma.sync.aligned.m16n8k16.row.col.f32.f16.f16.f32 "
        "{%0,%1,%2,%3}, {%4,%5,%6,%7}, {%8,%9}, {%0,%1,%2,%3};\n"
        : "+f"(d[0]), "+f"(d[1]), "+f"(d[2]), "+f"(d[3])
        : "r"(a[0]), "r"(a[1]), "r"(a[2]), "r"(a[3]), "r"(b[0]), "r"(b[1]));
}

__device__ __forceinline__ float gelu1(float x) {
    float x3 = x * x * x;
    return 0.5f * x * (1.f + tanhf(0.7978845608028654f * (x + 0.044715f * x3)));
}

// ================== FP16 NT GEMM: 3-stage cp.async, 1 sync/iter ==================
// C[b,m,n] = sum_k A[b,m,k]*B[b,n,k]  (+bias)(*gate)(+resid)(gelu)
// 128x128 CTA tile, 4 warps of 64x64, 128 threads.
#define BKH   32
#define LDS_K 40                 // padded row stride (halves)
#define STGB  (256*LDS_K*2)      // 20480 B per stage (128 A rows + 128 B rows)
#define NST   3
#define GSMEM (NST*STGB)         // 61440 B

__global__ __launch_bounds__(128, 2)
void gemm3(const __half* __restrict__ A, const __half* __restrict__ B,
           const float* __restrict__ bias, const float* __restrict__ resid,
           const float* __restrict__ gate,
           float* __restrict__ Cf, __half* __restrict__ Ch, int do_gelu,
           int K, int lda, int ldb, int ldc,
           long long sA, long long sB, long long sC)
{
    extern __shared__ __align__(16) char sm[];
    const uint32_t sbase = smem_to_u32(sm);

    const int tid  = threadIdx.x;
    const int lane = tid & 31;
    const int gid  = lane >> 2;
    const int tg   = lane & 3;
    const int warp = tid >> 5;
    const int wm   = (warp >> 1) * 64;
    const int wn   = (warp & 1) * 64;

    const int bm0 = blockIdx.x * 128;
    const int bn0 = blockIdx.y * 128;
    const __half* Ab = A + (size_t)blockIdx.z * sA + (size_t)bm0 * lda;
    const __half* Bb = B + (size_t)blockIdx.z * sB + (size_t)bn0 * ldb;

    float acc[4][8][4];
#pragma unroll
    for (int i = 0; i < 4; ++i)
#pragma unroll
        for (int j = 0; j < 8; ++j)
#pragma unroll
            for (int v = 0; v < 4; ++v) acc[i][j][v] = 0.f;

    const int nk = K / BKH;

#define LOAD_STAGE(k0, st) do {                                              \
    _Pragma("unroll")                                                        \
    for (int _i = 0; _i < 8; ++_i) {                                         \
        const int _idx = tid + _i * 128;                                     \
        const int _r = _idx >> 2, _c = _idx & 3;                             \
        const __half* _src = (_r < 128)                                      \
            ? Ab + (size_t)_r * lda + (k0) + _c * 8                          \
            : Bb + (size_t)(_r - 128) * ldb + (k0) + _c * 8;                 \
        cp16(sbase + (st) * STGB + _r * (LDS_K * 2) + _c * 16, _src);        \
    }                                                                        \
    CP_COMMIT();                                                             \
} while (0)

    // prologue: stages 0,1
    LOAD_STAGE(0, 0);
    LOAD_STAGE(BKH, 1);

    int slot = 0, nslot = 2;   // slot being computed; slot for next load
    for (int kt = 0; kt < nk; ++kt) {
        if (kt == nk - 1) CP_WAIT0(); else CP_WAIT1();
        __syncthreads();
        // issue loads for stage kt+2 BEFORE compute (slot was computed at kt-1)
        if (kt + 2 < nk) {
            const int k0 = (kt + 2) * BKH;
            LOAD_STAGE(k0, nslot);
        }
        const __half* Ss = (const __half*)(sm + slot * STGB);
#pragma unroll
        for (int ks = 0; ks < 2; ++ks) {
            const int kb = ks * 16 + 2 * tg;
            uint32_t af[4][4];
#pragma unroll
            for (int im = 0; im < 4; ++im) {
                const __half* ap = Ss + (wm + im * 16 + gid) * LDS_K + kb;
                af[im][0] = *(const uint32_t*)(ap);
                af[im][1] = *(const uint32_t*)(ap + 8 * LDS_K);
                af[im][2] = *(const uint32_t*)(ap + 8);
                af[im][3] = *(const uint32_t*)(ap + 8 * LDS_K + 8);
            }
            uint32_t bf[8][2];
#pragma unroll
            for (int in = 0; in < 8; ++in) {
                const __half* bp = Ss + (128 + wn + in * 8 + gid) * LDS_K + kb;
                bf[in][0] = *(const uint32_t*)(bp);
                bf[in][1] = *(const uint32_t*)(bp + 8);
            }
#pragma unroll
            for (int im = 0; im < 4; ++im)
#pragma unroll
                for (int in = 0; in < 8; ++in)
                    mma16(acc[im][in], af[im], bf[in]);
        }
        slot  = (slot  + 1 == NST) ? 0 : slot  + 1;
        nslot = (nslot + 1 == NST) ? 0 : nslot + 1;
    }
#undef LOAD_STAGE

    // ---------------- epilogue ----------------
    if (Ch) {
        __half* Cb = Ch + (size_t)blockIdx.z * sC;
#pragma unroll
        for (int im = 0; im < 4; ++im)
#pragma unroll
            for (int in = 0; in < 8; ++in) {
                const int r = bm0 + wm + im * 16 + gid;
                const int c = bn0 + wn + in * 8 + 2 * tg;
                float v0 = acc[im][in][0], v1 = acc[im][in][1];
                float v2 = acc[im][in][2], v3 = acc[im][in][3];
                if (bias) {
                    const float2 bb = *(const float2*)(bias + c);
                    v0 += bb.x; v1 += bb.y; v2 += bb.x; v3 += bb.y;
                }
                if (do_gelu) {
                    v0 = gelu1(v0); v1 = gelu1(v1); v2 = gelu1(v2); v3 = gelu1(v3);
                }
                *(__half2*)(Cb + (size_t)r * ldc + c)       = __floats2half2_rn(v0, v1);
                *(__half2*)(Cb + (size_t)(r + 8) * ldc + c) = __floats2half2_rn(v2, v3);
            }
    } else {
        float* Cb = Cf + (size_t)blockIdx.z * sC;
#pragma unroll
        for (int im = 0; im < 4; ++im)
#pragma unroll
            for (int in = 0; in < 8; ++in) {
                const int r = bm0 + wm + im * 16 + gid;
                const int c = bn0 + wn + in * 8 + 2 * tg;
                float v0 = acc[im][in][0], v1 = acc[im][in][1];
                float v2 = acc[im][in][2], v3 = acc[im][in][3];
                if (bias) {
                    const float2 bb = *(const float2*)(bias + c);
                    v0 += bb.x; v1 += bb.y; v2 += bb.x; v3 += bb.y;
                }
                if (gate) {
                    const float2 gg = *(const float2*)(gate + c);
                    v0 *= gg.x; v1 *= gg.y; v2 *= gg.x; v3 *= gg.y;
                }
                if (resid) {
                    const float2 r0 = *(const float2*)(resid + (size_t)r * ldc + c);
                    const float2 r1 = *(const float2*)(resid + (size_t)(r + 8) * ldc + c);
                    v0 += r0.x; v1 += r0.y; v2 += r1.x; v3 += r1.y;
                }
                *(float2*)(Cb + (size_t)r * ldc + c)       = make_float2(v0, v1);
                *(float2*)(Cb + (size_t)(r + 8) * ldc + c) = make_float2(v2, v3);
            }
    }
}

// ================= small kernels =================

__global__ void conv_f2h(const float* __restrict__ src, __half* __restrict__ dst) {
    const size_t i = (size_t)blockIdx.x * blockDim.x + threadIdx.x;
    float4 v = ((const float4*)src)[i];
    ((__half2*)dst)[2*i]   = __floats2half2_rn(v.x, v.y);
    ((__half2*)dst)[2*i+1] = __floats2half2_rn(v.z, v.w);
}

__global__ void silu_k(const float* __restrict__ v) {
    int i = blockIdx.x * blockDim.x + threadIdx.x;
    float x = v[i];
    g_svec[i] = x / (1.f + __expf(-x));
}

__global__ __launch_bounds__(256)
void mod_gemv(const float* __restrict__ W, const float* __restrict__ b) {
    const int warp = threadIdx.x >> 5, lane = threadIdx.x & 31;
    const int row  = blockIdx.x * 8 + warp;
    const float* w = W + (size_t)row * HID;
    float s = 0.f;
    for (int j = lane * 4; j < HID; j += 128) {
        float4 wv = *(const float4*)(w + j);
        float4 vv = *(const float4*)(g_svec + j);
        s += wv.x * vv.x + wv.y * vv.y + wv.z * vv.z + wv.w * vv.w;
    }
    #pragma unroll
    for (int o = 16; o; o >>= 1) s += __shfl_down_sync(0xffffffffu, s, o);
    if (!lane) g_mod[row] = s + b[row];
}

__global__ __launch_bounds__(256)
void ln_mod(const float* __restrict__ x) {
    const int l = blockIdx.x, tid = threadIdx.x;
    const float* xr = x + (size_t)l * HID;
    float4 v[3];
    float sum = 0.f, ss = 0.f;
    #pragma unroll
    for (int i = 0; i < 3; ++i) {
        v[i] = *(const float4*)(xr + (tid + i * 256) * 4);
        sum += v[i].x + v[i].y + v[i].z + v[i].w;
        ss  += v[i].x * v[i].x + v[i].y * v[i].y + v[i].z * v[i].z + v[i].w * v[i].w;
    }
    __shared__ float rs[2][8];
    #pragma unroll
    for (int o = 16; o; o >>= 1) {
        sum += __shfl_down_sync(0xffffffffu, sum, o);
        ss  += __shfl_down_sync(0xffffffffu, ss,  o);
    }
    if (!(tid & 31)) { rs[0][tid >> 5] = sum; rs[1][tid >> 5] = ss; }
    __syncthreads();
    sum = 0.f; ss = 0.f;
    #pragma unroll
    for (int i = 0; i < 8; ++i) { sum += rs[0][i]; ss += rs[1][i]; }
    const float mu   = sum * (1.f / HID);
    const float var  = ss * (1.f / HID) - mu * mu;
    const float rstd = rsqrtf(var + 1e-6f);
    #pragma unroll
    for (int i = 0; i < 3; ++i) {
        const int c = (tid + i * 256) * 4;
        float4 sh = *(const float4*)(g_mod + c);
        float4 sc = *(const float4*)(g_mod + HID + c);
        float ox = (1.f + sc.x) * ((v[i].x - mu) * rstd) + sh.x;
        float oy = (1.f + sc.y) * ((v[i].y - mu) * rstd) + sh.y;
        float oz = (1.f + sc.z) * ((v[i].z - mu) * rstd) + sh.z;
        float ow = (1.f + sc.w) * ((v[i].w - mu) * rstd) + sh.w;
        __half2* p = (__half2*)(g_xmodh + (size_t)l * HID + c);
        p[0] = __floats2half2_rn(ox, oy);
        p[1] = __floats2half2_rn(oz, ow);
    }
}

__global__ void qkv_prep(const float* __restrict__ pe,
                         const float* __restrict__ qs, const float* __restrict__ ks) {
    const int head = blockIdx.x, l = blockIdx.y, j = threadIdx.x;
    const __half* hr = g_qkvh + (size_t)l * H1Q + head * HD;
    float q0 = __half2float(hr[2*j]),         q1 = __half2float(hr[2*j + 1]);
    float k0 = __half2float(hr[HID + 2*j]),   k1 = __half2float(hr[HID + 2*j + 1]);
    float v0 = __half2float(hr[2*HID + 2*j]), v1 = __half2float(hr[2*HID + 2*j + 1]);

    float sq = q0*q0 + q1*q1, sk = k0*k0 + k1*k1;
    #pragma unroll
    for (int o = 16; o; o >>= 1) {
        sq += __shfl_down_sync(0xffffffffu, sq, o);
        sk += __shfl_down_sync(0xffffffffu, sk, o);
    }
    __shared__ float red[2][2];
    const int w = j >> 5, lane = j & 31;
    if (!lane) { red[0][w] = sq; red[1][w] = sk; }
    __syncthreads();
    const float rq = rsqrtf((red[0][0] + red[0][1]) * (1.f / HD) + 1e-6f);
    const float rk = rsqrtf((red[1][0] + red[1][1]) * (1.f / HD) + 1e-6f);

    q0 = q0 * rq * qs[2*j]; q1 = q1 * rq * qs[2*j + 1];
    k0 = k0 * rk * ks[2*j]; k1 = k1 * rk * ks[2*j + 1];

    const float* p = pe + ((size_t)l * (HD/2) + j) * 4;
    const float p00 = p[0], p01 = p[1], p10 = p[2], p11 = p[3];
    const float qo0 = p00 * q0 + p01 * q1, qo1 = p10 * q0 + p11 * q1;
    const float ko0 = p00 * k0 + p01 * k1, ko1 = p10 * k0 + p11 * k1;

    const float sm = 0.08838834764831845f;  // 1/sqrt(128)
    const size_t qoff = ((size_t)head * SEQL + l) * HD + 2*j;
    *(__half2*)(g_qh + qoff) = __floats2half2_rn(qo0 * sm, qo1 * sm);
    *(__half2*)(g_kh + qoff) = __floats2half2_rn(ko0, ko1);
    const size_t voff = ((size_t)head * HD + 2*j) * SEQL + l;
    g_vth[voff]        = __float2half_rn(v0);
    g_vth[voff + SEQL] = __float2half_rn(v1);
}

__global__ __launch_bounds__(256)
void softmax_k() {
    const float* p = g_sf + (size_t)blockIdx.x * SEQL;
    __half2* q = (__half2*)(g_ph + (size_t)blockIdx.x * SEQL);
    const int tid = threadIdx.x;
    float4 v0 = *(const float4*)(p + tid * 4);
    float4 v1 = *(const float4*)(p + 1024 + tid * 4);
    float mx = fmaxf(fmaxf(fmaxf(v0.x, v0.y), fmaxf(v0.z, v0.w)),
                     fmaxf(fmaxf(v1.x, v1.y), fmaxf(v1.z, v1.w)));
    __shared__ float rs[8];
    #pragma unroll
    for (int o = 16; o; o >>= 1) mx = fmaxf(mx, __shfl_xor_sync(0xffffffffu, mx, o));
    if (!(tid & 31)) rs[tid >> 5] = mx;
    __syncthreads();
    float gmx = rs[0];
    #pragma unroll
    for (int i = 1; i < 8; ++i) gmx = fmaxf(gmx, rs[i]);
    __syncthreads();
    float sm = 0.f;
    v0.x = __expf(v0.x - gmx); sm += v0.x;  v0.y = __expf(v0.y - gmx); sm += v0.y;
    v0.z = __expf(v0.z - gmx); sm += v0.z;  v0.w = __expf(v0.w - gmx); sm += v0.w;
    v1.x = __expf(v1.x - gmx); sm += v1.x;  v1.y = __expf(v1.y - gmx); sm += v1.y;
    v1.z = __expf(v1.z - gmx); sm += v1.z;  v1.w = __expf(v1.w - gmx); sm += v1.w;
    #pragma unroll
    for (int o = 16; o; o >>= 1) sm += __shfl_xor_sync(0xffffffffu, sm, o);
    if (!(tid & 31)) rs[tid >> 5] = sm;
    __syncthreads();
    float gs = 0.f;
    #pragma unroll
    for (int i = 0; i < 8; ++i) gs += rs[i];
    const float inv = 1.f / gs;
    q[tid*2]       = __floats2half2_rn(v0.x * inv, v0.y * inv);
    q[tid*2+1]     = __floats2half2_rn(v0.z * inv, v0.w * inv);
    q[512+tid*2]   = __floats2half2_rn(v1.x * inv, v1.y * inv);
    q[512+tid*2+1] = __floats2half2_rn(v1.z * inv, v1.w * inv);
}

// ================= launcher =================
extern "C" void kernel_launch(void* const* d_in, const int* in_sizes, int n_in,
                              void* d_out, int out_size) {
    const float* x       = (const float*)d_in[0];
    const float* vec     = (const float*)d_in[1];
    const float* pe      = (const float*)d_in[2];
    const float* mod_w   = (const float*)d_in[3];
    const float* mod_b   = (const float*)d_in[4];
    const float* lin1_w  = (const float*)d_in[5];
    const float* lin1_b  = (const float*)d_in[6];
    const float* lin2_w  = (const float*)d_in[7];
    const float* lin2_b  = (const float*)d_in[8];
    const float* q_scale = (const float*)d_in[9];
    const float* k_scale = (const float*)d_in[10];
    float* out = (float*)d_out;

    float *p_mod, *p_sf;
    __half *p_xmodh, *p_w1h, *p_w2h, *p_qkvh, *p_qh, *p_kh, *p_vth, *p_ph, *p_ch;
    cudaGetSymbolAddress((void**)&p_mod,   g_mod);
    cudaGetSymbolAddress((void**)&p_sf,    g_sf);
    cudaGetSymbolAddress((void**)&p_xmodh, g_xmodh);
    cudaGetSymbolAddress((void**)&p_w1h,   g_w1h);
    cudaGetSymbolAddress((void**)&p_w2h,   g_w2h);
    cudaGetSymbolAddress((void**)&p_qkvh,  g_qkvh);
    cudaGetSymbolAddress((void**)&p_qh,    g_qh);
    cudaGetSymbolAddress((void**)&p_kh,    g_kh);
    cudaGetSymbolAddress((void**)&p_vth,   g_vth);
    cudaGetSymbolAddress((void**)&p_ph,    g_ph);
    cudaGetSymbolAddress((void**)&p_ch,    g_ch);

    cudaFuncSetAttribute(gemm3, cudaFuncAttributeMaxDynamicSharedMemorySize, GSMEM);

    // 0) weight conversions (measured cheaper than in-GEMM staging)
    conv_f2h<<<((size_t)(H1Q + MLP) * HID / 4) / 256, 256>>>(lin1_w, p_w1h);
    conv_f2h<<<((size_t)HID * C2K / 4) / 256, 256>>>(lin2_w, p_w2h);

    // 1) modulation vector
    silu_k<<<HID / 256, 256>>>(vec);
    mod_gemv<<<(3 * HID) / 8, 256>>>(mod_w, mod_b);

    // 2) layernorm + modulation -> half
    ln_mod<<<SEQL, 256>>>(x);

    // 3a) lin1 qkv part -> half, bias fused
    gemm3<<<dim3(SEQL / 128, H1Q / 128), 128, GSMEM>>>(
        p_xmodh, p_w1h, lin1_b, nullptr, nullptr, nullptr, p_qkvh, 0,
        HID, HID, HID, H1Q, 0, 0, 0);

    // 3b) lin1 mlp part -> fused bias+GELU into concat cols [HID:)
    gemm3<<<dim3(SEQL / 128, MLP / 128), 128, GSMEM>>>(
        p_xmodh, p_w1h + (size_t)H1Q * HID, lin1_b + H1Q, nullptr, nullptr,
        nullptr, p_ch + HID, 1,
        HID, HID, HID, C2K, 0, 0, 0);

    // 4) qkv prep (rmsnorm + rope + V transpose)
    qkv_prep<<<dim3(HEADS, SEQL), 64>>>(pe, q_scale, k_scale);

    // 5) scores = q @ k^T (batched over heads) -> fp32
    gemm3<<<dim3(SEQL / 128, SEQL / 128, HEADS), 128, GSMEM>>>(
        p_qh, p_kh, nullptr, nullptr, nullptr, p_sf, nullptr, 0,
        HD, HD, HD, SEQL,
        (long long)SEQL * HD, (long long)SEQL * HD, (long long)SEQL * SEQL);

    // 6) softmax -> half probs
    softmax_k<<<HEADS * SEQL, 256>>>();

    // 7) attn = P @ V -> half concat cols [0:HID), head-interleaved
    gemm3<<<dim3(SEQL / 128, HD / 128, HEADS), 128, GSMEM>>>(
        p_ph, p_vth, nullptr, nullptr, nullptr, nullptr, p_ch, 0,
        SEQL, SEQL, SEQL, C2K,
        (long long)SEQL * SEQL, (long long)HD * SEQL, (long long)HD);

    // 8) lin2 + gate + residual fused: out = x + gate * (c @ lin2_w^T + b)
    gemm3<<<dim3(SEQL / 128, HID / 128), 128, GSMEM>>>(
        p_ch, p_w2h, lin2_b, x, p_mod + 2 * HID, out, nullptr, 0,
        C2K, C2K, C2K, HID, 0, 0, 0);
}

// round 17
// speedup vs baseline: 1.1372x; 1.0272x over previous
#include <cuda_runtime.h>
#include <cuda_fp16.h>
#include <cstdint>
#include <cstddef>

// ---------------- problem constants ----------------
#define HID   3072
#define HEADS 24
#define HD    128
#define SEQL  2048
#define MLP   12288
#define H1Q   (3*HID)         // 9216
#define C2K   (HID + MLP)     // 15360

// ---------------- device scratch (static, no allocations) ----------------
__device__ float  g_svec[HID];
__device__ float  g_mod [3*HID];                        // shift | scale | gate
__device__ __half g_xmodh[(size_t)SEQL*HID];            // modulated LN(x)
__device__ __half g_w1h [(size_t)(H1Q+MLP)*HID];        // lin1_w half
__device__ __half g_w2h [(size_t)HID*C2K];              // lin2_w half
__device__ __half g_qkvh[(size_t)SEQL*H1Q];             // lin1 qkv out
__device__ __half g_qh  [(size_t)HEADS*SEQL*HD];
__device__ __half g_kh  [(size_t)HEADS*SEQL*HD];
__device__ __half g_vth [(size_t)HEADS*HD*SEQL];        // v transposed [h][d][l]
__device__ __half g_ph  [(size_t)HEADS*SEQL*SEQL];      // scores -> probs (half, in place)
__device__ __half g_ch  [(size_t)SEQL*C2K];             // concat(attn, gelu)

// ---------------- helpers ----------------
__device__ __forceinline__ uint32_t smem_to_u32(const void* p) {
    uint32_t a;
    asm("{ .reg .u64 t; cvta.to.shared.u64 t, %1; cvt.u32.u64 %0, t; }" : "=r"(a) : "l"(p));
    return a;
}
__device__ __forceinline__ void cp16(uint32_t dst, const void* src) {
    asm volatile("cp.async.cg.shared.global [%0], [%1], 16;" :: "r"(dst), "l"(src) : "memory");
}
#define CP_COMMIT() asm volatile("cp.async.commit_group;" ::: "memory")
#define CP_WAIT2()  asm volatile("cp.async.wait_group 2;" ::: "memory")
#define CP_WAIT1()  asm volatile("cp.async.wait_group 1;" ::: "memory")
#define CP_WAIT0()  asm volatile("cp.async.wait_group 0;" ::: "memory")

__device__ __forceinline__ void mma16(float* d, const uint32_t* a, const uint32_t* b) {
    asm volatile(
        "mma.sync.aligned.m16n8k16.row.col.f32.f16.f16.f32 "
        "{%0,%1,%2,%3}, {%4,%5,%6,%7}, {%8,%9}, {%0,%1,%2,%3};\n"
        : "+f"(d[0]), "+f"(d[1]), "+f"(d[2]), "+f"(d[3])
        : "r"(a[0]), "r"(a[1]), "r"(a[2]), "r"(a[3]), "r"(b[0]), "r"(b[1]));
}

__device__ __forceinline__ float gelu1(float x) {
    float x3 = x * x * x;
    return 0.5f * x * (1.f + tanhf(0.7978845608028654f * (x + 0.044715f * x3)));
}

// ================== FP16 NT GEMM: 4-stage cp.async, 1 sync/iter ==================
// C[b,m,n] = sum_k A[b,m,k]*B[b,n,k]  (+bias)(*gate)(+resid)(gelu)
// 128x128 CTA tile, 4 warps of 64x64, 128 threads. Requires K/32 >= 3.
#define BKH   32
#define LDS_K 40                 // padded row stride (halves)
#define STGB  (256*LDS_K*2)      // 20480 B per stage (128 A rows + 128 B rows)
#define NST   4
#define GSMEM (NST*STGB)         // 81920 B

__global__ __launch_bounds__(128, 2)
void gemm3(const __half* __restrict__ A, const __half* __restrict__ B,
           const float* __restrict__ bias, const float* __restrict__ resid,
           const float* __restrict__ gate,
           float* __restrict__ Cf, __half* __restrict__ Ch, int do_gelu,
           int K, int lda, int ldb, int ldc,
           long long sA, long long sB, long long sC)
{
    extern __shared__ __align__(16) char sm[];
    const uint32_t sbase = smem_to_u32(sm);

    const int tid  = threadIdx.x;
    const int lane = tid & 31;
    const int gid  = lane >> 2;
    const int tg   = lane & 3;
    const int warp = tid >> 5;
    const int wm   = (warp >> 1) * 64;
    const int wn   = (warp & 1) * 64;

    const int bm0 = blockIdx.x * 128;
    const int bn0 = blockIdx.y * 128;
    const __half* Ab = A + (size_t)blockIdx.z * sA + (size_t)bm0 * lda;
    const __half* Bb = B + (size_t)blockIdx.z * sB + (size_t)bn0 * ldb;

    float acc[4][8][4];
#pragma unroll
    for (int i = 0; i < 4; ++i)
#pragma unroll
        for (int j = 0; j < 8; ++j)
#pragma unroll
            for (int v = 0; v < 4; ++v) acc[i][j][v] = 0.f;

    const int nk = K / BKH;

#define LOAD_STAGE(k0, st) do {                                              \
    _Pragma("unroll")                                                        \
    for (int _i = 0; _i < 8; ++_i) {                                         \
        const int _idx = tid + _i * 128;                                     \
        const int _r = _idx >> 2, _c = _idx & 3;                             \
        const __half* _src = (_r < 128)                                      \
            ? Ab + (size_t)_r * lda + (k0) + _c * 8                          \
            : Bb + (size_t)(_r - 128) * ldb + (k0) + _c * 8;                 \
        cp16(sbase + (st) * STGB + _r * (LDS_K * 2) + _c * 16, _src);        \
    }                                                                        \
    CP_COMMIT();                                                             \
} while (0)

    // prologue: stages 0,1,2
    LOAD_STAGE(0, 0);
    LOAD_STAGE(BKH, 1);
    LOAD_STAGE(2 * BKH, 2);

    for (int kt = 0; kt < nk; ++kt) {
        if (kt < nk - 2)       CP_WAIT2();
        else if (kt == nk - 2) CP_WAIT1();
        else                   CP_WAIT0();
        __syncthreads();
        // issue stage kt+3 into slot (kt+3)%4 == (kt-1)%4 (computed at kt-1)
        if (kt + 3 < nk) {
            const int k0 = (kt + 3) * BKH;
            const int ns = (kt + 3) & 3;
            LOAD_STAGE(k0, ns);
        }
        const int slot = kt & 3;
        const __half* Ss = (const __half*)(sm + slot * STGB);
#pragma unroll
        for (int ks = 0; ks < 2; ++ks) {
            const int kb = ks * 16 + 2 * tg;
            uint32_t af[4][4];
#pragma unroll
            for (int im = 0; im < 4; ++im) {
                const __half* ap = Ss + (wm + im * 16 + gid) * LDS_K + kb;
                af[im][0] = *(const uint32_t*)(ap);
                af[im][1] = *(const uint32_t*)(ap + 8 * LDS_K);
                af[im][2] = *(const uint32_t*)(ap + 8);
                af[im][3] = *(const uint32_t*)(ap + 8 * LDS_K + 8);
            }
            uint32_t bf[8][2];
#pragma unroll
            for (int in = 0; in < 8; ++in) {
                const __half* bp = Ss + (128 + wn + in * 8 + gid) * LDS_K + kb;
                bf[in][0] = *(const uint32_t*)(bp);
                bf[in][1] = *(const uint32_t*)(bp + 8);
            }
#pragma unroll
            for (int im = 0; im < 4; ++im)
#pragma unroll
                for (int in = 0; in < 8; ++in)
                    mma16(acc[im][in], af[im], bf[in]);
        }
    }
#undef LOAD_STAGE

    // ---------------- epilogue ----------------
    if (Ch) {
        __half* Cb = Ch + (size_t)blockIdx.z * sC;
#pragma unroll
        for (int im = 0; im < 4; ++im)
#pragma unroll
            for (int in = 0; in < 8; ++in) {
                const int r = bm0 + wm + im * 16 + gid;
                const int c = bn0 + wn + in * 8 + 2 * tg;
                float v0 = acc[im][in][0], v1 = acc[im][in][1];
                float v2 = acc[im][in][2], v3 = acc[im][in][3];
                if (bias) {
                    const float2 bb = *(const float2*)(bias + c);
                    v0 += bb.x; v1 += bb.y; v2 += bb.x; v3 += bb.y;
                }
                if (do_gelu) {
                    v0 = gelu1(v0); v1 = gelu1(v1); v2 = gelu1(v2); v3 = gelu1(v3);
                }
                *(__half2*)(Cb + (size_t)r * ldc + c)       = __floats2half2_rn(v0, v1);
                *(__half2*)(Cb + (size_t)(r + 8) * ldc + c) = __floats2half2_rn(v2, v3);
            }
    } else {
        float* Cb = Cf + (size_t)blockIdx.z * sC;
#pragma unroll
        for (int im = 0; im < 4; ++im)
#pragma unroll
            for (int in = 0; in < 8; ++in) {
                const int r = bm0 + wm + im * 16 + gid;
                const int c = bn0 + wn + in * 8 + 2 * tg;
                float v0 = acc[im][in][0], v1 = acc[im][in][1];
                float v2 = acc[im][in][2], v3 = acc[im][in][3];
                if (bias) {
                    const float2 bb = *(const float2*)(bias + c);
                    v0 += bb.x; v1 += bb.y; v2 += bb.x; v3 += bb.y;
                }
                if (gate) {
                    const float2 gg = *(const float2*)(gate + c);
                    v0 *= gg.x; v1 *= gg.y; v2 *= gg.x; v3 *= gg.y;
                }
                if (resid) {
                    const float2 r0 = *(const float2*)(resid + (size_t)r * ldc + c);
                    const float2 r1 = *(const float2*)(resid + (size_t)(r + 8) * ldc + c);
                    v0 += r0.x; v1 += r0.y; v2 += r1.x; v3 += r1.y;
                }
                *(float2*)(Cb + (size_t)r * ldc + c)       = make_float2(v0, v1);
                *(float2*)(Cb + (size_t)(r + 8) * ldc + c) = make_float2(v2, v3);
            }
    }
}

// ================= small kernels =================

__global__ void conv_f2h(const float* __restrict__ src, __half* __restrict__ dst) {
    const size_t i = (size_t)blockIdx.x * blockDim.x + threadIdx.x;
    float4 v = ((const float4*)src)[i];
    ((__half2*)dst)[2*i]   = __floats2half2_rn(v.x, v.y);
    ((__half2*)dst)[2*i+1] = __floats2half2_rn(v.z, v.w);
}

__global__ void silu_k(const float* __restrict__ v) {
    int i = blockIdx.x * blockDim.x + threadIdx.x;
    float x = v[i];
    g_svec[i] = x / (1.f + __expf(-x));
}

__global__ __launch_bounds__(256)
void mod_gemv(const float* __restrict__ W, const float* __restrict__ b) {
    const int warp = threadIdx.x >> 5, lane = threadIdx.x & 31;
    const int row  = blockIdx.x * 8 + warp;
    const float* w = W + (size_t)row * HID;
    float s = 0.f;
    for (int j = lane * 4; j < HID; j += 128) {
        float4 wv = *(const float4*)(w + j);
        float4 vv = *(const float4*)(g_svec + j);
        s += wv.x * vv.x + wv.y * vv.y + wv.z * vv.z + wv.w * vv.w;
    }
    #pragma unroll
    for (int o = 16; o; o >>= 1) s += __shfl_down_sync(0xffffffffu, s, o);
    if (!lane) g_mod[row] = s + b[row];
}

__global__ __launch_bounds__(256)
void ln_mod(const float* __restrict__ x) {
    const int l = blockIdx.x, tid = threadIdx.x;
    const float* xr = x + (size_t)l * HID;
    float4 v[3];
    float sum = 0.f, ss = 0.f;
    #pragma unroll
    for (int i = 0; i < 3; ++i) {
        v[i] = *(const float4*)(xr + (tid + i * 256) * 4);
        sum += v[i].x + v[i].y + v[i].z + v[i].w;
        ss  += v[i].x * v[i].x + v[i].y * v[i].y + v[i].z * v[i].z + v[i].w * v[i].w;
    }
    __shared__ float rs[2][8];
    #pragma unroll
    for (int o = 16; o; o >>= 1) {
        sum += __shfl_down_sync(0xffffffffu, sum, o);
        ss  += __shfl_down_sync(0xffffffffu, ss,  o);
    }
    if (!(tid & 31)) { rs[0][tid >> 5] = sum; rs[1][tid >> 5] = ss; }
    __syncthreads();
    sum = 0.f; ss = 0.f;
    #pragma unroll
    for (int i = 0; i < 8; ++i) { sum += rs[0][i]; ss += rs[1][i]; }
    const float mu   = sum * (1.f / HID);
    const float var  = ss * (1.f / HID) - mu * mu;
    const float rstd = rsqrtf(var + 1e-6f);
    #pragma unroll
    for (int i = 0; i < 3; ++i) {
        const int c = (tid + i * 256) * 4;
        float4 sh = *(const float4*)(g_mod + c);
        float4 sc = *(const float4*)(g_mod + HID + c);
        float ox = (1.f + sc.x) * ((v[i].x - mu) * rstd) + sh.x;
        float oy = (1.f + sc.y) * ((v[i].y - mu) * rstd) + sh.y;
        float oz = (1.f + sc.z) * ((v[i].z - mu) * rstd) + sh.z;
        float ow = (1.f + sc.w) * ((v[i].w - mu) * rstd) + sh.w;
        __half2* p = (__half2*)(g_xmodh + (size_t)l * HID + c);
        p[0] = __floats2half2_rn(ox, oy);
        p[1] = __floats2half2_rn(oz, ow);
    }
}

__global__ void qkv_prep(const float* __restrict__ pe,
                         const float* __restrict__ qs, const float* __restrict__ ks) {
    const int head = blockIdx.x, l = blockIdx.y, j = threadIdx.x;
    const __half* hr = g_qkvh + (size_t)l * H1Q + head * HD;
    float q0 = __half2float(hr[2*j]),         q1 = __half2float(hr[2*j + 1]);
    float k0 = __half2float(hr[HID + 2*j]),   k1 = __half2float(hr[HID + 2*j + 1]);
    float v0 = __half2float(hr[2*HID + 2*j]), v1 = __half2float(hr[2*HID + 2*j + 1]);

    float sq = q0*q0 + q1*q1, sk = k0*k0 + k1*k1;
    #pragma unroll
    for (int o = 16; o; o >>= 1) {
        sq += __shfl_down_sync(0xffffffffu, sq, o);
        sk += __shfl_down_sync(0xffffffffu, sk, o);
    }
    __shared__ float red[2][2];
    const int w = j >> 5, lane = j & 31;
    if (!lane) { red[0][w] = sq; red[1][w] = sk; }
    __syncthreads();
    const float rq = rsqrtf((red[0][0] + red[0][1]) * (1.f / HD) + 1e-6f);
    const float rk = rsqrtf((red[1][0] + red[1][1]) * (1.f / HD) + 1e-6f);

    q0 = q0 * rq * qs[2*j]; q1 = q1 * rq * qs[2*j + 1];
    k0 = k0 * rk * ks[2*j]; k1 = k1 * rk * ks[2*j + 1];

    const float* p = pe + ((size_t)l * (HD/2) + j) * 4;
    const float p00 = p[0], p01 = p[1], p10 = p[2], p11 = p[3];
    const float qo0 = p00 * q0 + p01 * q1, qo1 = p10 * q0 + p11 * q1;
    const float ko0 = p00 * k0 + p01 * k1, ko1 = p10 * k0 + p11 * k1;

    const float sm = 0.08838834764831845f;  // 1/sqrt(128)
    const size_t qoff = ((size_t)head * SEQL + l) * HD + 2*j;
    *(__half2*)(g_qh + qoff) = __floats2half2_rn(qo0 * sm, qo1 * sm);
    *(__half2*)(g_kh + qoff) = __floats2half2_rn(ko0, ko1);
    const size_t voff = ((size_t)head * HD + 2*j) * SEQL + l;
    g_vth[voff]        = __float2half_rn(v0);
    g_vth[voff + SEQL] = __float2half_rn(v1);
}

// row softmax over 2048, in place on half scores. 1 uint4 (8 halves) per thread.
__global__ __launch_bounds__(256)
void softmax_k() {
    uint4* p = (uint4*)(g_ph + (size_t)blockIdx.x * SEQL);
    const int tid = threadIdx.x;
    uint4 u = p[tid];
    __half2 h[4];
    *(uint32_t*)&h[0] = u.x; *(uint32_t*)&h[1] = u.y;
    *(uint32_t*)&h[2] = u.z; *(uint32_t*)&h[3] = u.w;
    float f[8];
#pragma unroll
    for (int i = 0; i < 4; ++i) {
        float2 t = __half22float2(h[i]);
        f[2*i] = t.x; f[2*i+1] = t.y;
    }
    float mx = f[0];
#pragma unroll
    for (int i = 1; i < 8; ++i) mx = fmaxf(mx, f[i]);
    __shared__ float rs[8];
#pragma unroll
    for (int o = 16; o; o >>= 1) mx = fmaxf(mx, __shfl_xor_sync(0xffffffffu, mx, o));
    if (!(tid & 31)) rs[tid >> 5] = mx;
    __syncthreads();
    float gmx = rs[0];
#pragma unroll
    for (int i = 1; i < 8; ++i) gmx = fmaxf(gmx, rs[i]);
    __syncthreads();
    float sm = 0.f;
#pragma unroll
    for (int i = 0; i < 8; ++i) { f[i] = __expf(f[i] - gmx); sm += f[i]; }
#pragma unroll
    for (int o = 16; o; o >>= 1) sm += __shfl_xor_sync(0xffffffffu, sm, o);
    if (!(tid & 31)) rs[tid >> 5] = sm;
    __syncthreads();
    float gs = 0.f;
#pragma unroll
    for (int i = 0; i < 8; ++i) gs += rs[i];
    const float inv = 1.f / gs;
#pragma unroll
    for (int i = 0; i < 4; ++i)
        h[i] = __floats2half2_rn(f[2*i] * inv, f[2*i+1] * inv);
    u.x = *(uint32_t*)&h[0]; u.y = *(uint32_t*)&h[1];
    u.z = *(uint32_t*)&h[2]; u.w = *(uint32_t*)&h[3];
    p[tid] = u;
}

// ================= launcher =================
extern "C" void kernel_launch(void* const* d_in, const int* in_sizes, int n_in,
                              void* d_out, int out_size) {
    const float* x       = (const float*)d_in[0];
    const float* vec     = (const float*)d_in[1];
    const float* pe      = (const float*)d_in[2];
    const float* mod_w   = (const float*)d_in[3];
    const float* mod_b   = (const float*)d_in[4];
    const float* lin1_w  = (const float*)d_in[5];
    const float* lin1_b  = (const float*)d_in[6];
    const float* lin2_w  = (const float*)d_in[7];
    const float* lin2_b  = (const float*)d_in[8];
    const float* q_scale = (const float*)d_in[9];
    const float* k_scale = (const float*)d_in[10];
    float* out = (float*)d_out;

    float *p_mod;
    __half *p_xmodh, *p_w1h, *p_w2h, *p_qkvh, *p_qh, *p_kh, *p_vth, *p_ph, *p_ch;
    cudaGetSymbolAddress((void**)&p_mod,   g_mod);
    cudaGetSymbolAddress((void**)&p_xmodh, g_xmodh);
    cudaGetSymbolAddress((void**)&p_w1h,   g_w1h);
    cudaGetSymbolAddress((void**)&p_w2h,   g_w2h);
    cudaGetSymbolAddress((void**)&p_qkvh,  g_qkvh);
    cudaGetSymbolAddress((void**)&p_qh,    g_qh);
    cudaGetSymbolAddress((void**)&p_kh,    g_kh);
    cudaGetSymbolAddress((void**)&p_vth,   g_vth);
    cudaGetSymbolAddress((void**)&p_ph,    g_ph);
    cudaGetSymbolAddress((void**)&p_ch,    g_ch);

    cudaFuncSetAttribute(gemm3, cudaFuncAttributeMaxDynamicSharedMemorySize, GSMEM);

    // 0) weight conversions
    conv_f2h<<<((size_t)(H1Q + MLP) * HID / 4) / 256, 256>>>(lin1_w, p_w1h);
    conv_f2h<<<((size_t)HID * C2K / 4) / 256, 256>>>(lin2_w, p_w2h);

    // 1) modulation vector
    silu_k<<<HID / 256, 256>>>(vec);
    mod_gemv<<<(3 * HID) / 8, 256>>>(mod_w, mod_b);

    // 2) layernorm + modulation -> half
    ln_mod<<<SEQL, 256>>>(x);

    // 3a) lin1 qkv part -> half, bias fused
    gemm3<<<dim3(SEQL / 128, H1Q / 128), 128, GSMEM>>>(
        p_xmodh, p_w1h, lin1_b, nullptr, nullptr, nullptr, p_qkvh, 0,
        HID, HID, HID, H1Q, 0, 0, 0);

    // 3b) lin1 mlp part -> fused bias+GELU into concat cols [HID:)
    gemm3<<<dim3(SEQL / 128, MLP / 128), 128, GSMEM>>>(
        p_xmodh, p_w1h + (size_t)H1Q * HID, lin1_b + H1Q, nullptr, nullptr,
        nullptr, p_ch + HID, 1,
        HID, HID, HID, C2K, 0, 0, 0);

    // 4) qkv prep (rmsnorm + rope + V transpose)
    qkv_prep<<<dim3(HEADS, SEQL), 64>>>(pe, q_scale, k_scale);

    // 5) scores = q @ k^T (batched over heads) -> HALF directly into g_ph
    gemm3<<<dim3(SEQL / 128, SEQL / 128, HEADS), 128, GSMEM>>>(
        p_qh, p_kh, nullptr, nullptr, nullptr, nullptr, p_ph, 0,
        HD, HD, HD, SEQL,
        (long long)SEQL * HD, (long long)SEQL * HD, (long long)SEQL * SEQL);

    // 6) softmax in place on half scores -> half probs
    softmax_k<<<HEADS * SEQL, 256>>>();

    // 7) attn = P @ V -> half concat cols [0:HID), head-interleaved
    gemm3<<<dim3(SEQL / 128, HD / 128, HEADS), 128, GSMEM>>>(
        p_ph, p_vth, nullptr, nullptr, nullptr, nullptr, p_ch, 0,
        SEQL, SEQL, SEQL, C2K,
        (long long)SEQL * SEQL, (long long)HD * SEQL, (long long)HD);

    // 8) lin2 + gate + residual fused: out = x + gate * (c @ lin2_w^T + b)
    gemm3<<<dim3(SEQL / 128, HID / 128), 128, GSMEM>>>(
        p_ch, p_w2h, lin2_b, x, p_mod + 2 * HID, out, nullptr, 0,
        C2K, C2K, C2K, HID, 0, 0, 0);
}